// round 11
// baseline (speedup 1.0000x reference)
#include <cuda_runtime.h>

// Problem constants (fixed by the dataset)
#define CC   24
#define NPTS 1536
#define HV   40
#define EPSF 1e-8f
#define T_PEN 0.1f
#define R_PEN 1.0f
#define B1   256
#define B2   256
#define PPT  (NPTS / B2)   // 6 points per thread, exact

// ---------------------------------------------------------------------------
// Device scratch (no allocations allowed)
// ---------------------------------------------------------------------------
__device__ float2 g_pts  [CC * NPTS];  // transformed points (pads -> 1e30 sentinel)
__device__ float4 g_edges[CC * HV];    // ex, ey, c0, 1/(len+eps)  (compacted)
__device__ int    g_nv   [CC];         // valid edge count
__device__ float4 g_hbb  [CC];         // hull bbox, EXPANDED: xmin,xmax,ymin,ymax
__device__ float4 g_pbb  [CC];         // point bbox:            xmin,xmax,ymin,ymax

// ---------------------------------------------------------------------------
// Stage 1: one block per cluster. Transform points (once), point bbox,
// transform hull, compact edges, hull bbox. Block 0 also writes the penalty
// terms into out[0] (re-initializing the accumulator each graph replay).
// ---------------------------------------------------------------------------
__global__ __launch_bounds__(B1)
void csep_stage1(const float2* __restrict__ pts,
                 const float2* __restrict__ hulls,
                 const float2* __restrict__ medoids,
                 const float*  __restrict__ angles,
                 const float2* __restrict__ trans,
                 float* __restrict__ out) {
    const int c   = blockIdx.x;
    const int tid = threadIdx.x;

    __shared__ float2 shull[HV];
    __shared__ int    s_nv;
    __shared__ float4 swbb[B1 / 32];

    if (c == 0 && tid == 0) {
        float s = 0.0f;
        #pragma unroll
        for (int k = 0; k < CC; ++k) {
            float ak = angles[k];
            float2 tk = trans[k];
            s += R_PEN * ak * ak + T_PEN * (tk.x * tk.x + tk.y * tk.y);
        }
        out[0] = s;
    }

    const float a  = angles[c];
    const float ca = cosf(a), sa = sinf(a);
    const float2 m = medoids[c];
    const float2 t = trans[c];
    const float ox = m.x + t.x, oy = m.y + t.y;

    // ---- points: batched loads (MLP), transform, sentinel pads, bbox ----
    const float2* src = pts   + (size_t)c * NPTS;
    float2*       dst = g_pts + (size_t)c * NPTS;
    float2 r[PPT];
    #pragma unroll
    for (int u = 0; u < PPT; ++u) r[u] = src[tid + u * B1];

    float mnx = 3.4e38f, mxx = -3.4e38f, mny = 3.4e38f, mxy = -3.4e38f;
    #pragma unroll
    for (int u = 0; u < PPT; ++u) {
        float2 p = r[u];
        float2 o;
        if (p.x == 0.0f && p.y == 0.0f) {        // padded (exact zeros in input)
            o = make_float2(1e30f, 1e30f);       // fails any bbox test downstream
        } else {
            float cx = p.x - m.x, cy = p.y - m.y;
            o.x = cx * ca - cy * sa + ox;
            o.y = cx * sa + cy * ca + oy;
            mnx = fminf(mnx, o.x); mxx = fmaxf(mxx, o.x);
            mny = fminf(mny, o.y); mxy = fmaxf(mxy, o.y);
        }
        dst[tid + u * B1] = o;
    }

    // ---- hull transform ----
    if (tid == 0) s_nv = 0;
    if (tid < HV) {
        float2 h = hulls[c * HV + tid];
        float cx = h.x - m.x, cy = h.y - m.y;
        shull[tid] = make_float2(cx * ca - cy * sa + ox,
                                 cx * sa + cy * ca + oy);
    }
    __syncthreads();

    // ---- edges (compact valid) + hull bbox ----
    if (tid < HV) {
        float2 p1 = shull[tid];
        float2 p2 = shull[(tid + 1) % HV];
        float ex = p2.x - p1.x, ey = p2.y - p1.y;
        float len = sqrtf(ex * ex + ey * ey);
        if (len > 1e-6f) {                       // evalid (reference-exact)
            int k = atomicAdd(&s_nv, 1);
            g_edges[c * HV + k] = make_float4(ex, ey,
                                              ex * p1.y - ey * p1.x,
                                              1.0f / (len + EPSF));
        }
    }
    if (tid == B1 - 1) {                         // different warp than edge work
        float hx0 = shull[0].x, hx1 = hx0, hy0 = shull[0].y, hy1 = hy0;
        #pragma unroll
        for (int k = 1; k < HV; ++k) {
            float2 p = shull[k];
            hx0 = fminf(hx0, p.x); hx1 = fmaxf(hx1, p.x);
            hy0 = fminf(hy0, p.y); hy1 = fmaxf(hy1, p.y);
        }
        const float M = 0.05f;   // margin >> fp error of signed distance
        g_hbb[c] = make_float4(hx0 - M, hx1 + M, hy0 - M, hy1 + M);
    }

    // ---- point-bbox block reduction ----
    #pragma unroll
    for (int o = 16; o > 0; o >>= 1) {
        mnx = fminf(mnx, __shfl_xor_sync(0xffffffffu, mnx, o));
        mxx = fmaxf(mxx, __shfl_xor_sync(0xffffffffu, mxx, o));
        mny = fminf(mny, __shfl_xor_sync(0xffffffffu, mny, o));
        mxy = fmaxf(mxy, __shfl_xor_sync(0xffffffffu, mxy, o));
    }
    const int wid = tid >> 5, lid = tid & 31;
    if (lid == 0) swbb[wid] = make_float4(mnx, mxx, mny, mxy);
    __syncthreads();
    if (tid == 0) {
        float4 b = swbb[0];
        #pragma unroll
        for (int w = 1; w < B1 / 32; ++w) {
            float4 q = swbb[w];
            b.x = fminf(b.x, q.x); b.y = fmaxf(b.y, q.y);
            b.z = fminf(b.z, q.z); b.w = fmaxf(b.w, q.w);
        }
        g_pbb[c] = b;
        g_nv[c]  = s_nv;
    }
}

// ---------------------------------------------------------------------------
// Stage 2: one block per (i = point cluster, j = hull cluster) pair.
// Exact pair-level early exit via bbox intersection, then batched point
// loads (already transformed) -> per-point bbox filter -> edge loop.
// ---------------------------------------------------------------------------
__global__ __launch_bounds__(B2)
void csep_stage2(float* __restrict__ out) {
    const int i = blockIdx.x;
    const int j = blockIdx.y;
    if (i == j) return;

    // pair-level exact prefilter (uniform across block)
    const float4 pb = g_pbb[i];          // xmin,xmax,ymin,ymax of points i
    const float4 hb = g_hbb[j];          // expanded hull bbox of j
    if (pb.x > hb.y || pb.y < hb.x || pb.z > hb.w || pb.w < hb.z) return;
    const int nv = g_nv[j];
    if (nv < 3) return;                  // hull_ok false

    __shared__ float4 sedge[HV];
    __shared__ float  swsum[B2 / 32];

    const int tid = threadIdx.x;
    if (tid < nv) sedge[tid] = g_edges[j * HV + tid];
    __syncthreads();

    // batched point loads: all PPT loads in flight before any use
    const float2* ptsi = g_pts + (size_t)i * NPTS;
    float2 r[PPT];
    #pragma unroll
    for (int u = 0; u < PPT; ++u) r[u] = ptsi[tid + u * B2];

    float local = 0.0f;
    #pragma unroll
    for (int u = 0; u < PPT; ++u) {
        const float px = r[u].x, py = r[u].y;   // pads are 1e30 -> fail bbox
        if (px < hb.x || px > hb.y || py < hb.z || py > hb.w) continue;

        float minabs = 3.4e38f;
        bool pos = true, neg = true;
        #pragma unroll 4
        for (int k = 0; k < nv; ++k) {
            float4 e = sedge[k];
            float s = (e.x * py - e.y * px - e.z) * e.w;
            minabs = fminf(minabs, fabsf(s));
            pos = pos && (s >= -EPSF);
            neg = neg && (s <=  EPSF);
        }
        if (pos || neg)
            local += 1.0f / (1.0f + expf(-minabs));   // sigmoid(min_abs)
    }

    // block reduction
    #pragma unroll
    for (int o = 16; o > 0; o >>= 1)
        local += __shfl_down_sync(0xffffffffu, local, o);
    const int wid = tid >> 5, lid = tid & 31;
    if (lid == 0) swsum[wid] = local;
    __syncthreads();
    if (wid == 0) {
        float v = (lid < (B2 / 32)) ? swsum[lid] : 0.0f;
        #pragma unroll
        for (int o = (B2 / 64); o > 0; o >>= 1)
            v += __shfl_down_sync(0xffffffffu, v, o);
        if (lid == 0 && v != 0.0f)
            atomicAdd(out, v);   // SEP_W == 1.0
    }
}

// ---------------------------------------------------------------------------
// Launch. Inputs (metadata order):
//  0: padded_clusters (C,N,2) f32   1: padded_hulls (C,H,2) f32
//  2: medoids (C,2) f32             3: rotation_angles (C,) f32
//  4: translations (C,2) f32        5: cluster_masks (unused)
//  6: hull_masks (unused)
// ---------------------------------------------------------------------------
extern "C" void kernel_launch(void* const* d_in, const int* in_sizes, int n_in,
                              void* d_out, int out_size) {
    const float2* pts     = (const float2*)d_in[0];
    const float2* hulls   = (const float2*)d_in[1];
    const float2* medoids = (const float2*)d_in[2];
    const float*  angles  = (const float*) d_in[3];
    const float2* trans   = (const float2*)d_in[4];
    float* out = (float*)d_out;

    csep_stage1<<<CC, B1>>>(pts, hulls, medoids, angles, trans, out);

    dim3 grid(CC, CC);
    csep_stage2<<<grid, B2>>>(out);
}

// round 12
// speedup vs baseline: 1.1950x; 1.1950x over previous
#include <cuda_runtime.h>

// Problem constants (fixed by the dataset)
#define CC    24
#define NPTS  1536
#define HV    40
#define EPSF  1e-8f
#define T_PEN 0.1f
#define R_PEN 1.0f
#define BLK   256
#define SLICES (NPTS / BLK)   // 6 slices -> exactly 1 point per thread

// ---------------------------------------------------------------------------
// Kernel 1 (tiny): out[0] = rotation + translation penalties.
// Also re-initializes the accumulator on every graph replay.
// ---------------------------------------------------------------------------
__global__ void csep_init(const float* __restrict__ angles,
                          const float2* __restrict__ trans,
                          float* __restrict__ out) {
    const int l = threadIdx.x;
    float s = 0.0f;
    if (l < CC) {
        float a  = angles[l];
        float2 t = trans[l];
        s = R_PEN * a * a + T_PEN * (t.x * t.x + t.y * t.y);
    }
    #pragma unroll
    for (int o = 16; o > 0; o >>= 1)
        s += __shfl_down_sync(0xffffffffu, s, o);
    if (l == 0) out[0] = s;
}

// ---------------------------------------------------------------------------
// Kernel 2: fully fused. One block per (slice, j = hull cluster, i = point
// cluster). Each thread owns exactly ONE point. The block:
//   - transforms hull j into shared (threads 0..39)
//   - each thread transforms its own point of cluster i
//   - warp 0 computes the expanded hull bbox (exact prefilter for `inside`)
//   - threads 0..39 compact valid edges (exact: zero-length pad edges drop)
//   - __syncthreads_or early-exit if no point survives the bbox test
//   - survivors run the smin/smax edge loop; block reduce; atomicAdd
// ---------------------------------------------------------------------------
__global__ __launch_bounds__(BLK)
void csep_main(const float2* __restrict__ pts,    // [C*N]
               const float2* __restrict__ hulls,  // [C*H]
               const float2* __restrict__ medoids,// [C]
               const float*  __restrict__ angles, // [C]
               const float2* __restrict__ trans,  // [C]
               float* __restrict__ out) {
    const int slice = blockIdx.x;   // 0..SLICES-1
    const int j     = blockIdx.y;   // hull cluster
    const int i     = blockIdx.z;   // point cluster
    if (i == j) return;             // offdiag mask

    __shared__ float2 shull[HV];
    __shared__ float4 sedge[HV];    // ex, -ey, -c0, 1/(len+eps)
    __shared__ int    s_nv;
    __shared__ float  sbb[4];       // expanded hull bbox
    __shared__ float  swsum[BLK / 32];

    const int tid = threadIdx.x;

    // ---- hull j transform (threads 0..39) ----
    if (tid < HV) {
        if (tid == 0) s_nv = 0;
        float aj = angles[j];
        float cj = cosf(aj), sj = sinf(aj);
        float2 mj = medoids[j];
        float2 tj = trans[j];
        float2 h = hulls[j * HV + tid];
        float cx = h.x - mj.x, cy = h.y - mj.y;
        shull[tid] = make_float2(cx * cj - cy * sj + (mj.x + tj.x),
                                 cx * sj + cy * cj + (mj.y + tj.y));
    }

    // ---- own point transform (all threads, overlaps hull work) ----
    float px = 1e30f, py = 1e30f;          // pads fail any bbox test
    {
        float2 p = pts[(size_t)i * NPTS + slice * BLK + tid];
        if (!(p.x == 0.0f && p.y == 0.0f)) {   // padded points are exact zeros
            float ai = angles[i];
            float ci = cosf(ai), si = sinf(ai);
            float2 mi = medoids[i];
            float2 ti = trans[i];
            float cx = p.x - mi.x, cy = p.y - mi.y;
            px = cx * ci - cy * si + (mi.x + ti.x);
            py = cx * si + cy * ci + (mi.y + ti.y);
        }
    }
    __syncthreads();

    // ---- expanded hull bbox: warp 0 via shuffles ----
    if (tid < 32) {
        float2 v1 = shull[tid];
        float2 v2 = (tid + 32 < HV) ? shull[tid + 32] : v1;
        float mnx = fminf(v1.x, v2.x), mxx = fmaxf(v1.x, v2.x);
        float mny = fminf(v1.y, v2.y), mxy = fmaxf(v1.y, v2.y);
        #pragma unroll
        for (int o = 16; o > 0; o >>= 1) {
            mnx = fminf(mnx, __shfl_xor_sync(0xffffffffu, mnx, o));
            mxx = fmaxf(mxx, __shfl_xor_sync(0xffffffffu, mxx, o));
            mny = fminf(mny, __shfl_xor_sync(0xffffffffu, mny, o));
            mxy = fmaxf(mxy, __shfl_xor_sync(0xffffffffu, mxy, o));
        }
        if (tid == 0) {
            const float M = 0.05f;   // margin >> fp error of signed distance
            sbb[0] = mnx - M; sbb[1] = mxx + M;
            sbb[2] = mny - M; sbb[3] = mxy + M;
        }
    }

    // ---- edges: compact the valid ones (threads 0..39) ----
    if (tid < HV) {
        float2 p1 = shull[tid];
        float2 p2 = shull[(tid + 1) % HV];
        float ex = p2.x - p1.x, ey = p2.y - p1.y;
        float len = sqrtf(ex * ex + ey * ey);
        if (len > 1e-6f) {                   // evalid (reference-exact)
            int k = atomicAdd(&s_nv, 1);
            sedge[k] = make_float4(ex, -ey,
                                   -(ex * p1.y - ey * p1.x),
                                   1.0f / (len + EPSF));
        }
    }
    __syncthreads();

    const int nv = s_nv;                     // uniform
    if (nv < 3) return;                      // hull_ok false

    bool survive = (px >= sbb[0]) & (px <= sbb[1]) &
                   (py >= sbb[2]) & (py <= sbb[3]);
    if (!__syncthreads_or(survive)) return;  // exact: no point can be inside

    float local = 0.0f;
    if (survive) {
        float smin = 3.4e38f, smax = -3.4e38f;
        #pragma unroll 4
        for (int k = 0; k < nv; ++k) {
            float4 e = sedge[k];
            float t = fmaf(e.x, py, e.z);    //  ex*py - c0
            t = fmaf(e.y, px, t);            // -ey*px + ...
            float s = t * e.w;               // / (len+eps)
            smin = fminf(smin, s);
            smax = fmaxf(smax, s);
        }
        bool pos = (smin >= -EPSF);
        bool neg = (smax <=  EPSF);
        if (pos | neg) {
            float minabs = pos ? fabsf(smin) : fabsf(smax);
            local = __fdividef(1.0f, 1.0f + __expf(-minabs));  // sigmoid
        }
    }

    // ---- block reduction ----
    #pragma unroll
    for (int o = 16; o > 0; o >>= 1)
        local += __shfl_down_sync(0xffffffffu, local, o);
    const int wid = tid >> 5, lid = tid & 31;
    if (lid == 0) swsum[wid] = local;
    __syncthreads();
    if (wid == 0) {
        float v = (lid < (BLK / 32)) ? swsum[lid] : 0.0f;
        #pragma unroll
        for (int o = (BLK / 64); o > 0; o >>= 1)
            v += __shfl_down_sync(0xffffffffu, v, o);
        if (lid == 0 && v != 0.0f)
            atomicAdd(out, v);   // SEP_W == 1.0
    }
}

// ---------------------------------------------------------------------------
// Launch. Inputs (metadata order):
//  0: padded_clusters (C,N,2) f32   1: padded_hulls (C,H,2) f32
//  2: medoids (C,2) f32             3: rotation_angles (C,) f32
//  4: translations (C,2) f32        5: cluster_masks (unused)
//  6: hull_masks (unused)
// ---------------------------------------------------------------------------
extern "C" void kernel_launch(void* const* d_in, const int* in_sizes, int n_in,
                              void* d_out, int out_size) {
    const float2* pts     = (const float2*)d_in[0];
    const float2* hulls   = (const float2*)d_in[1];
    const float2* medoids = (const float2*)d_in[2];
    const float*  angles  = (const float*) d_in[3];
    const float2* trans   = (const float2*)d_in[4];
    float* out = (float*)d_out;

    csep_init<<<1, 32>>>(angles, trans, out);

    dim3 grid(SLICES, CC, CC);
    csep_main<<<grid, BLK>>>(pts, hulls, medoids, angles, trans, out);
}

// round 13
// speedup vs baseline: 1.4269x; 1.1940x over previous
#include <cuda_runtime.h>

// Problem constants (fixed by the dataset)
#define CC     24
#define NPTS   1536
#define HV     40
#define EPSF   1e-8f
#define T_PEN  0.1f
#define R_PEN  1.0f
#define BLK    256
#define SLICES (NPTS / BLK)      // 6 slices, exactly 1 point per thread
#define FINF   3.4e38f

// ---------------------------------------------------------------------------
// Device scratch (no allocations allowed)
// ---------------------------------------------------------------------------
__device__ float2 g_pts  [CC * NPTS];        // transformed pts (pads -> 1e30)
__device__ float4 g_edges[CC * HV];          // ex, -ey, -c0, 1/(len+eps)
__device__ int    g_nv   [CC];               // valid edge count
__device__ float4 g_hbb  [CC];               // expanded hull bbox
__device__ float4 g_pbb  [CC * SLICES];      // per-(cluster,slice) point bbox

// ---------------------------------------------------------------------------
// Stage 1: grid (SLICES, CC), 256 threads, 1 point per thread.
//  - thread 0 computes the cluster's cos/sin ONCE (shared)
//  - transform own point -> g_pts (pad sentinel), per-slice bbox -> g_pbb
//  - slice-0 blocks: hull transform, edge compaction, expanded hull bbox
//  - block (0,0): rotation+translation penalty -> out[0] (re-inits accumulator)
// ---------------------------------------------------------------------------
__global__ __launch_bounds__(BLK)
void csep_stage1(const float2* __restrict__ pts,
                 const float2* __restrict__ hulls,
                 const float2* __restrict__ medoids,
                 const float*  __restrict__ angles,
                 const float2* __restrict__ trans,
                 float* __restrict__ out) {
    const int slice = blockIdx.x;
    const int c     = blockIdx.y;
    const int tid   = threadIdx.x;

    __shared__ float  s_cs[2];        // cos, sin for cluster c
    __shared__ float2 shull[HV];
    __shared__ int    s_nv;
    __shared__ float4 swbb[BLK / 32];

    if (tid == 0) {
        float sv, cv;
        sincosf(angles[c], &sv, &cv);
        s_cs[0] = cv; s_cs[1] = sv;
        s_nv = 0;
    }

    // penalty (block (0,0), warp 1 — doesn't collide with thread 0's work)
    if (slice == 0 && c == 0 && tid >= 32 && tid < 64) {
        const int l = tid - 32;
        float s = 0.0f;
        if (l < CC) {
            float a  = angles[l];
            float2 t = trans[l];
            s = R_PEN * a * a + T_PEN * (t.x * t.x + t.y * t.y);
        }
        #pragma unroll
        for (int o = 16; o > 0; o >>= 1)
            s += __shfl_down_sync(0xffffffffu, s, o);
        if (l == 0) out[0] = s;
    }
    __syncthreads();

    const float ca = s_cs[0], sa = s_cs[1];
    const float2 m = medoids[c];
    const float2 t = trans[c];
    const float ox = m.x + t.x, oy = m.y + t.y;

    // ---- own point ----
    const int pidx = c * NPTS + slice * BLK + tid;
    float2 p = pts[pidx];
    float px = 1e30f, py = 1e30f;
    float mnx = FINF, mxx = -FINF, mny = FINF, mxy = -FINF;
    if (!(p.x == 0.0f && p.y == 0.0f)) {     // padded points are exact zeros
        float cx = p.x - m.x, cy = p.y - m.y;
        px = cx * ca - cy * sa + ox;
        py = cx * sa + cy * ca + oy;
        mnx = px; mxx = px; mny = py; mxy = py;
    }
    g_pts[pidx] = make_float2(px, py);

    // ---- hull (slice-0 blocks only) ----
    if (slice == 0 && tid < HV) {
        float2 h = hulls[c * HV + tid];
        float cx = h.x - m.x, cy = h.y - m.y;
        shull[tid] = make_float2(cx * ca - cy * sa + ox,
                                 cx * sa + cy * ca + oy);
    }
    __syncthreads();

    if (slice == 0) {
        if (tid < HV) {
            float2 p1 = shull[tid];
            float2 p2 = shull[(tid + 1) % HV];
            float ex = p2.x - p1.x, ey = p2.y - p1.y;
            float len = sqrtf(ex * ex + ey * ey);
            if (len > 1e-6f) {               // evalid (reference-exact)
                int k = atomicAdd(&s_nv, 1);
                g_edges[c * HV + k] = make_float4(ex, -ey,
                                                  -(ex * p1.y - ey * p1.x),
                                                  1.0f / (len + EPSF));
            }
        }
        if (tid == BLK - 1) {                // different warp than edge work
            float hx0 = shull[0].x, hx1 = hx0, hy0 = shull[0].y, hy1 = hy0;
            #pragma unroll
            for (int k = 1; k < HV; ++k) {
                float2 q = shull[k];
                hx0 = fminf(hx0, q.x); hx1 = fmaxf(hx1, q.x);
                hy0 = fminf(hy0, q.y); hy1 = fmaxf(hy1, q.y);
            }
            const float M = 0.05f;           // margin >> fp signed-dist error
            g_hbb[c] = make_float4(hx0 - M, hx1 + M, hy0 - M, hy1 + M);
        }
    }

    // ---- per-slice point bbox reduction ----
    #pragma unroll
    for (int o = 16; o > 0; o >>= 1) {
        mnx = fminf(mnx, __shfl_xor_sync(0xffffffffu, mnx, o));
        mxx = fmaxf(mxx, __shfl_xor_sync(0xffffffffu, mxx, o));
        mny = fminf(mny, __shfl_xor_sync(0xffffffffu, mny, o));
        mxy = fmaxf(mxy, __shfl_xor_sync(0xffffffffu, mxy, o));
    }
    const int wid = tid >> 5, lid = tid & 31;
    if (lid == 0) swbb[wid] = make_float4(mnx, mxx, mny, mxy);
    __syncthreads();
    if (tid == 0) {
        float4 b = swbb[0];
        #pragma unroll
        for (int w = 1; w < BLK / 32; ++w) {
            float4 q = swbb[w];
            b.x = fminf(b.x, q.x); b.y = fmaxf(b.y, q.y);
            b.z = fminf(b.z, q.z); b.w = fmaxf(b.w, q.w);
        }
        g_pbb[c * SLICES + slice] = b;
        if (slice == 0) g_nv[c] = s_nv;      // s_nv final (post-sync)
    }
}

// ---------------------------------------------------------------------------
// Stage 2: grid (SLICES, CC=j hull, CC=i points), 256 threads, 1 pt/thread.
// Exit path = two cached float4 loads + compare. No trig, no transforms.
// ---------------------------------------------------------------------------
__global__ __launch_bounds__(BLK)
void csep_stage2(float* __restrict__ out) {
    const int slice = blockIdx.x;
    const int j     = blockIdx.y;
    const int i     = blockIdx.z;
    if (i == j) return;

    // exact pair(slice)-level prefilter
    const float4 pb = g_pbb[i * SLICES + slice];
    const float4 hb = g_hbb[j];
    if (pb.x > hb.y || pb.y < hb.x || pb.z > hb.w || pb.w < hb.z) return;
    const int nv = g_nv[j];
    if (nv < 3) return;                      // hull_ok false

    __shared__ float4 sedge[HV];
    __shared__ float  swsum[BLK / 32];

    const int tid = threadIdx.x;
    if (tid < nv) sedge[tid] = g_edges[j * HV + tid];

    // own (already transformed) point; pads are 1e30 -> fail bbox
    float2 r = g_pts[(size_t)i * NPTS + slice * BLK + tid];
    const float px = r.x, py = r.y;
    bool survive = (px >= hb.x) & (px <= hb.y) & (py >= hb.z) & (py <= hb.w);
    if (!__syncthreads_or(survive)) return;  // also fences sedge

    float local = 0.0f;
    if (survive) {
        float smin = FINF, smax = -FINF;
        #pragma unroll 4
        for (int k = 0; k < nv; ++k) {
            float4 e = sedge[k];
            float v = fmaf(e.x, py, e.z);    //  ex*py - c0
            v = fmaf(e.y, px, v);            // -ey*px + ...
            float s = v * e.w;               // / (len+eps)
            smin = fminf(smin, s);
            smax = fmaxf(smax, s);
        }
        bool pos = (smin >= -EPSF);
        bool neg = (smax <=  EPSF);
        if (pos | neg) {
            float minabs = pos ? fabsf(smin) : fabsf(smax);
            local = __fdividef(1.0f, 1.0f + __expf(-minabs));  // sigmoid
        }
    }

    // block reduction
    #pragma unroll
    for (int o = 16; o > 0; o >>= 1)
        local += __shfl_down_sync(0xffffffffu, local, o);
    const int wid = tid >> 5, lid = tid & 31;
    if (lid == 0) swsum[wid] = local;
    __syncthreads();
    if (wid == 0) {
        float v = (lid < (BLK / 32)) ? swsum[lid] : 0.0f;
        #pragma unroll
        for (int o = (BLK / 64); o > 0; o >>= 1)
            v += __shfl_down_sync(0xffffffffu, v, o);
        if (lid == 0 && v != 0.0f)
            atomicAdd(out, v);               // SEP_W == 1.0
    }
}

// ---------------------------------------------------------------------------
// Launch. Inputs (metadata order):
//  0: padded_clusters (C,N,2) f32   1: padded_hulls (C,H,2) f32
//  2: medoids (C,2) f32             3: rotation_angles (C,) f32
//  4: translations (C,2) f32        5: cluster_masks (unused)
//  6: hull_masks (unused)
// ---------------------------------------------------------------------------
extern "C" void kernel_launch(void* const* d_in, const int* in_sizes, int n_in,
                              void* d_out, int out_size) {
    const float2* pts     = (const float2*)d_in[0];
    const float2* hulls   = (const float2*)d_in[1];
    const float2* medoids = (const float2*)d_in[2];
    const float*  angles  = (const float*) d_in[3];
    const float2* trans   = (const float2*)d_in[4];
    float* out = (float*)d_out;

    dim3 g1(SLICES, CC);
    csep_stage1<<<g1, BLK>>>(pts, hulls, medoids, angles, trans, out);

    dim3 g2(SLICES, CC, CC);
    csep_stage2<<<g2, BLK>>>(out);
}